// round 13
// baseline (speedup 1.0000x reference)
#include <cuda_runtime.h>
#include <cuda_bf16.h>
#include <cstdint>
#include <cstddef>

#define NB 32
#define NN 1024
#define NF 64
#define NO 128

typedef unsigned long long u64;
typedef uint32_t u32;

#define KC (-14.4269504089f)                 // -10 * log2(e)
#define INV_KC (-0.0693147181f)              // 1 / KC

// Device scratch: coefficients from pairwise stage
__device__ float c1v_g[NB * NN];
__device__ float c2v_g[NB * NN];

// A repacked as bf16 hi/lo, layout [n][k]: B_g[n*128+k] = A[k*128+n]
__device__ __align__(16) __nv_bfloat16 Bhi_g[128 * 128];
__device__ __align__(16) __nv_bfloat16 Blo_g[128 * 128];

__device__ __forceinline__ u32 smem_u32(const void* p) {
    u32 a;
    asm("{ .reg .u64 t; cvta.to.shared.u64 t, %1; cvt.u32.u64 %0, t; }" : "=r"(a) : "l"(p));
    return a;
}
__device__ __forceinline__ float fast_exp2(float t) {
    float r; asm("ex2.approx.f32 %0, %1;" : "=f"(r) : "f"(t)); return r;
}
__device__ __forceinline__ u64 pk2f(float lo, float hi) {
    u64 r; asm("mov.b64 %0, {%1, %2};" : "=l"(r) : "f"(lo), "f"(hi)); return r;
}
__device__ __forceinline__ void up2f(u64 v, float& a, float& b) {
    asm("mov.b64 {%0, %1}, %2;" : "=f"(a), "=f"(b) : "l"(v));
}
#define ADD2(d, a, b)   asm("add.rn.f32x2 %0, %1, %2;" : "=l"(d) : "l"(a), "l"(b))
#define FMA2IO(d, a, b) asm("fma.rn.f32x2 %0, %1, %2, %0;" : "+l"(d) : "l"(a), "l"(b))
#define ADD2ACC(d, a)   asm("add.rn.f32x2 %0, %1, %0;" : "+l"(d) : "l"(a))

#define LDSM_X4(r0, r1, r2, r3, addr) \
    asm volatile("ldmatrix.sync.aligned.m8n8.x4.shared.b16 {%0,%1,%2,%3}, [%4];" \
                 : "=r"(r0), "=r"(r1), "=r"(r2), "=r"(r3) : "r"(addr))

__device__ __forceinline__ void mma16816(float* d, const u32* a, const u32* b) {
    asm volatile(
        "mma.sync.aligned.m16n8k16.row.col.f32.bf16.bf16.f32 "
        "{%0,%1,%2,%3}, {%4,%5,%6,%7}, {%8,%9}, {%0,%1,%2,%3};"
        : "+f"(d[0]), "+f"(d[1]), "+f"(d[2]), "+f"(d[3])
        : "r"(a[0]), "r"(a[1]), "r"(a[2]), "r"(a[3]), "r"(b[0]), "r"(b[1]));
}

// ---------------------------------------------------------------------------
// Kernel 1: pairwise coefficients (+ A-conversion in the first 16 CTAs).
// grid = 512 (16/batch), 256 threads. q = t>>6 (warp-uniform i-quarter ->
// broadcast smem loads), jl = t&63. Unchanged from round 12.
// ---------------------------------------------------------------------------
__global__ void __launch_bounds__(256) coef_kernel(
    const float* __restrict__ x, const float* __restrict__ mask,
    const float* __restrict__ A)
{
    __shared__ __align__(16) float xs[NN];
    __shared__ __align__(16) float ys[NN];
    __shared__ __align__(16) float kz[NN];
    __shared__ float redw[4][64];
    __shared__ float redd[4][64];

    const int b = blockIdx.x >> 4;
    const int jbase = (blockIdx.x & 15) * 64;
    const int t = threadIdx.x;

    // A -> Bhi/Blo bf16 (blocks 0..15; gemm launches after, so visible)
    if (blockIdx.x < 16) {
        #pragma unroll
        for (int p = 0; p < 4; p++) {
            int idx = blockIdx.x * 1024 + p * 256 + t;   // 0..16383
            int n = idx >> 7, k = idx & 127;
            float a = A[k * 128 + n];
            __nv_bfloat16 h = __float2bfloat16_rn(a);
            Bhi_g[idx] = h;
            Blo_g[idx] = __float2bfloat16_rn(a - __bfloat162float(h));
        }
    }

    for (int i = t; i < NN; i += 256) {
        float2 c = *(const float2*)(x + ((size_t)b * NN + i) * NF + (NF - 2));
        xs[i] = c.x;
        ys[i] = c.y;
        kz[i] = KC * fmaf(c.y, c.y, c.x * c.x);
    }
    __syncthreads();

    const int q  = t >> 6;        // i-quarter, uniform within each warp
    const int jl = t & 63;
    const int j  = jbase + jl;
    const float Km2jx = -2.0f * KC * xs[j];
    const float Km2jy = -2.0f * KC * ys[j];
    const float Krj = kz[j];

    const u64 Kx2 = pk2f(Km2jx, Km2jx);
    const u64 Ky2 = pk2f(Km2jy, Km2jy);
    const u64 Kr2 = pk2f(Krj, Krj);

    const ulonglong2* X2 = (const ulonglong2*)(xs) + q * 64;
    const ulonglong2* Y2 = (const ulonglong2*)(ys) + q * 64;
    const ulonglong2* Z2 = (const ulonglong2*)(kz) + q * 64;

    u64 S1A = 0ULL, S2A = 0ULL, S1B = 0ULL, S2B = 0ULL;
    #pragma unroll 4
    for (int i = 0; i < 64; i++) {          // 4 points per iteration, broadcast loads
        ulonglong2 X = X2[i];
        ulonglong2 Y = Y2[i];
        ulonglong2 Z = Z2[i];

        u64 u0; ADD2(u0, Z.x, Kr2);
        FMA2IO(u0, Y.x, Ky2);
        FMA2IO(u0, X.x, Kx2);
        float ua, ub; up2f(u0, ua, ub);
        u64 e0 = pk2f(fast_exp2(ua), fast_exp2(ub));
        ADD2ACC(S1A, e0);
        FMA2IO(S2A, u0, e0);

        u64 u1; ADD2(u1, Z.y, Kr2);
        FMA2IO(u1, Y.y, Ky2);
        FMA2IO(u1, X.y, Kx2);
        float uc, ud; up2f(u1, uc, ud);
        u64 e1 = pk2f(fast_exp2(uc), fast_exp2(ud));
        ADD2ACC(S1B, e1);
        FMA2IO(S2B, u1, e1);
    }

    float a, bb, c, d;
    up2f(S1A, a, bb); up2f(S1B, c, d);
    float s1 = (a + bb) + (c + d);
    up2f(S2A, a, bb); up2f(S2B, c, d);
    float s2 = (a + bb) + (c + d);

    redw[q][jl] = s1;
    redd[q][jl] = s2;
    __syncthreads();

    if (t < 64) {
        float ws = (redw[0][t] + redw[1][t]) + (redw[2][t] + redw[3][t]);
        float dw = (redd[0][t] + redd[1][t]) + (redd[2][t] + redd[3][t]);
        int gj = b * NN + jbase + t;
        float m = mask[gj];
        c1v_g[gj] = fmaf(ws, m, -1.0f);
        c2v_g[gj] = (dw * INV_KC) * m;
    }
}

// ---------------------------------------------------------------------------
// Kernel 2: GEMM with c1 folded in (persistent: 2 tiles per CTA).
//   X2 = [x | c1*x]  (64 rows x K=128), bf16 hi/lo split (3 terms)
//   out = (X2 @ B + c2*A2 + bias) * m
// 512 threads (16 warps), warp tile 16r x 32c. grid = 256, 2 CTAs/SM ->
// 32 warps/SM for latency hiding. 104.4KB smem.
// ---------------------------------------------------------------------------
#define XROW 272
#define OFF_GXHI 0
#define OFF_GXLO (64 * XROW)                 // 17408
#define OFF_GBHI (2 * 64 * XROW)             // 34816
#define OFF_GBLO (OFF_GBHI + 128 * XROW)     // 69632
#define GSMEM_TOTAL (OFF_GBLO + 128 * XROW)  // 104448

__global__ void __launch_bounds__(512, 2) gemm_kernel(
    const float* __restrict__ x,
    const float* __restrict__ mask,
    const float* __restrict__ A,
    const float* __restrict__ bias,
    float* __restrict__ out)
{
    extern __shared__ __align__(16) char sm[];
    const u32 sbase = smem_u32(sm);
    const int t = threadIdx.x;
    const int wid = t >> 5;
    const int lane = t & 31;

    // ---- B tiles: bf16 globals -> padded smem rows (once per CTA) ----
    {
        const uint4* bh = (const uint4*)Bhi_g;
        const uint4* bl = (const uint4*)Blo_g;
        #pragma unroll
        for (int pass = 0; pass < 4; pass++) {
            int idx = pass * 512 + t;           // 0..2047: 128 rows x 16 chunks
            int row = idx >> 4, chunk = idx & 15;
            char* dst = sm + row * XROW + chunk * 16;
            *(uint4*)(dst + OFF_GBHI) = bh[idx];
            *(uint4*)(dst + OFF_GBLO) = bl[idx];
        }
    }

    // per-thread constants
    const int m0 = (wid & 3) * 16;       // 4 m-warps x 16 rows
    const int n0 = (wid >> 2) * 32;      // 4 n-warps x 32 cols
    const int g = lane >> 3, ri = lane & 7;
    const u32 arow = (u32)(ri + ((g & 1) << 3));
    const u32 acol = (u32)((g >> 1) << 4);
    const u32 brow = (u32)(ri + ((g >> 1) << 3));
    const u32 bcol = (u32)((g & 1) << 4);
    const u32 XhiB = sbase + OFF_GXHI + (m0 + arow) * XROW + acol;
    const u32 XloB = XhiB + (u32)(OFF_GXLO - OFF_GXHI);
    const u32 BhiB = sbase + OFF_GBHI + (n0 + brow) * XROW + bcol;
    const u32 BloB = BhiB + (u32)(OFF_GBLO - OFF_GBHI);
    const float* A2p = A + 128 * 128;

    #pragma unroll
    for (int tile = 0; tile < 2; tile++) {
        const int row0 = (blockIdx.x * 2 + tile) * 64;

        // ---- X2 = [x | c1*x] as bf16 hi/lo; 8 values/thread, STS.128 ----
        {
            int row  = t >> 3;                      // 0..63
            int cseg = (t & 7) * 8;                 // 8 cols each
            const float* xr = x + (size_t)(row0 + row) * NF + cseg;
            float c1 = c1v_g[row0 + row];
            float4 va = *(const float4*)(xr);
            float4 vb = *(const float4*)(xr + 4);
            float vs[8] = {va.x, va.y, va.z, va.w, vb.x, vb.y, vb.z, vb.w};
            u32 hi[4], lo[4], shi[4], slo[4];
            #pragma unroll
            for (int h = 0; h < 4; h++) {
                u32 hp = 0, lp = 0, shp = 0, slp = 0;
                #pragma unroll
                for (int e = 0; e < 2; e++) {
                    float vv = vs[h * 2 + e];
                    __nv_bfloat16 vh = __float2bfloat16_rn(vv);
                    __nv_bfloat16 vl = __float2bfloat16_rn(vv - __bfloat162float(vh));
                    float w = c1 * vv;
                    __nv_bfloat16 wh = __float2bfloat16_rn(w);
                    __nv_bfloat16 wl = __float2bfloat16_rn(w - __bfloat162float(wh));
                    hp  |= (u32)__bfloat16_as_ushort(vh) << (16 * e);
                    lp  |= (u32)__bfloat16_as_ushort(vl) << (16 * e);
                    shp |= (u32)__bfloat16_as_ushort(wh) << (16 * e);
                    slp |= (u32)__bfloat16_as_ushort(wl) << (16 * e);
                }
                hi[h] = hp; lo[h] = lp; shi[h] = shp; slo[h] = slp;
            }
            char* ph = sm + OFF_GXHI + row * XROW + cseg * 2;
            char* pl = sm + OFF_GXLO + row * XROW + cseg * 2;
            *(uint4*)(ph)        = make_uint4(hi[0], hi[1], hi[2], hi[3]);
            *(uint4*)(ph + 128)  = make_uint4(shi[0], shi[1], shi[2], shi[3]);  // c1*x half
            *(uint4*)(pl)        = make_uint4(lo[0], lo[1], lo[2], lo[3]);
            *(uint4*)(pl + 128)  = make_uint4(slo[0], slo[1], slo[2], slo[3]);
        }
        __syncthreads();

        // ---- mainloop: warp tile 16r x 32c ----
        float acc[4][4];
        #pragma unroll
        for (int nb = 0; nb < 4; nb++)
            #pragma unroll
            for (int e = 0; e < 4; e++)
                acc[nb][e] = 0.f;

        #pragma unroll
        for (int kb = 0; kb < 8; kb++) {
            const u32 koff = kb * 32;              // 16 k-elements = 32 bytes
            u32 ah[4], al[4];
            LDSM_X4(ah[0], ah[1], ah[2], ah[3], XhiB + koff);
            LDSM_X4(al[0], al[1], al[2], al[3], XloB + koff);

            u32 bh[4][2], bl[4][2];
            LDSM_X4(bh[0][0], bh[0][1], bh[1][0], bh[1][1], BhiB + koff);
            LDSM_X4(bh[2][0], bh[2][1], bh[3][0], bh[3][1], BhiB + 16 * XROW + koff);
            LDSM_X4(bl[0][0], bl[0][1], bl[1][0], bl[1][1], BloB + koff);
            LDSM_X4(bl[2][0], bl[2][1], bl[3][0], bl[3][1], BloB + 16 * XROW + koff);

            #pragma unroll
            for (int nb = 0; nb < 4; nb++) {
                mma16816(acc[nb], ah, bh[nb]);   // xhi * Bhi
                mma16816(acc[nb], al, bh[nb]);   // xlo * Bhi
                mma16816(acc[nb], ah, bl[nb]);   // xhi * Blo
            }
        }

        // ---- epilogue: out = (acc + c2*A2 + bias) * m ----
        {
            const int r1 = m0 + (lane >> 2);
            const int r2 = r1 + 8;
            const int gr1 = row0 + r1, gr2 = row0 + r2;
            const float m1 = mask[gr1], m2 = mask[gr2];
            const float c21 = c2v_g[gr1], c22 = c2v_g[gr2];
            #pragma unroll
            for (int nb = 0; nb < 4; nb++) {
                const int col = n0 + nb * 8 + (lane & 3) * 2;
                const float a20 = A2p[col], a21 = A2p[col + 1];
                const float b0 = bias[col], b1 = bias[col + 1];
                const float* gacc = acc[nb];
                float2 o1, o2;
                o1.x = (gacc[0] + fmaf(c21, a20, b0)) * m1;
                o1.y = (gacc[1] + fmaf(c21, a21, b1)) * m1;
                o2.x = (gacc[2] + fmaf(c22, a20, b0)) * m2;
                o2.y = (gacc[3] + fmaf(c22, a21, b1)) * m2;
                *(float2*)(out + (size_t)gr1 * NO + col) = o1;
                *(float2*)(out + (size_t)gr2 * NO + col) = o2;
            }
        }
        __syncthreads();   // X2 rewrite protection for next tile
    }
}

extern "C" void kernel_launch(void* const* d_in, const int* in_sizes, int n_in,
                              void* d_out, int out_size) {
    const float* x    = (const float*)d_in[0];
    const float* mask = (const float*)d_in[1];
    const float* A    = (const float*)d_in[2];
    const float* bias = (const float*)d_in[3];
    float* out = (float*)d_out;

    cudaFuncSetAttribute(gemm_kernel, cudaFuncAttributeMaxDynamicSharedMemorySize, GSMEM_TOTAL);

    coef_kernel<<<NB * 16, 256>>>(x, mask, A);
    gemm_kernel<<<(NB * NN) / 128, 512, GSMEM_TOTAL>>>(x, mask, A, bias, out);
}

// round 15
// speedup vs baseline: 1.1175x; 1.1175x over previous
#include <cuda_runtime.h>
#include <cuda_bf16.h>
#include <cstdint>
#include <cstddef>

#define NB 32
#define NN 1024
#define NF 64
#define NO 128

typedef unsigned long long u64;
typedef uint32_t u32;

#define KC (-14.4269504089f)                 // -10 * log2(e)
#define INV_KC (-0.0693147181f)              // 1 / KC

// Device scratch: coefficients from pairwise stage
__device__ float c1v_g[NB * NN];
__device__ float c2v_g[NB * NN];

// A repacked as bf16 hi/lo, layout [n][k]: B_g[n*128+k] = A[k*128+n]
__device__ __align__(16) __nv_bfloat16 Bhi_g[128 * 128];
__device__ __align__(16) __nv_bfloat16 Blo_g[128 * 128];

__device__ __forceinline__ u32 smem_u32(const void* p) {
    u32 a;
    asm("{ .reg .u64 t; cvta.to.shared.u64 t, %1; cvt.u32.u64 %0, t; }" : "=r"(a) : "l"(p));
    return a;
}
__device__ __forceinline__ float fast_exp2(float t) {
    float r; asm("ex2.approx.f32 %0, %1;" : "=f"(r) : "f"(t)); return r;
}
__device__ __forceinline__ u64 pk2f(float lo, float hi) {
    u64 r; asm("mov.b64 %0, {%1, %2};" : "=l"(r) : "f"(lo), "f"(hi)); return r;
}
__device__ __forceinline__ void up2f(u64 v, float& a, float& b) {
    asm("mov.b64 {%0, %1}, %2;" : "=f"(a), "=f"(b) : "l"(v));
}
#define ADD2(d, a, b)   asm("add.rn.f32x2 %0, %1, %2;" : "=l"(d) : "l"(a), "l"(b))
#define FMA2IO(d, a, b) asm("fma.rn.f32x2 %0, %1, %2, %0;" : "+l"(d) : "l"(a), "l"(b))
#define ADD2ACC(d, a)   asm("add.rn.f32x2 %0, %1, %0;" : "+l"(d) : "l"(a))

#define LDSM_X4(r0, r1, r2, r3, addr) \
    asm volatile("ldmatrix.sync.aligned.m8n8.x4.shared.b16 {%0,%1,%2,%3}, [%4];" \
                 : "=r"(r0), "=r"(r1), "=r"(r2), "=r"(r3) : "r"(addr))

__device__ __forceinline__ void mma16816(float* d, const u32* a, const u32* b) {
    asm volatile(
        "mma.sync.aligned.m16n8k16.row.col.f32.bf16.bf16.f32 "
        "{%0,%1,%2,%3}, {%4,%5,%6,%7}, {%8,%9}, {%0,%1,%2,%3};"
        : "+f"(d[0]), "+f"(d[1]), "+f"(d[2]), "+f"(d[3])
        : "r"(a[0]), "r"(a[1]), "r"(a[2]), "r"(a[3]), "r"(b[0]), "r"(b[1]));
}

// ---------------------------------------------------------------------------
// Kernel 1: pairwise coefficients (+ A-conversion in the first 16 CTAs).
// grid = 256 (8/batch), 512 threads. 128 j's per CTA; q = t>>7 is
// warp-uniform (broadcast smem loads), jl = t&127.
// ---------------------------------------------------------------------------
__global__ void __launch_bounds__(512) coef_kernel(
    const float* __restrict__ x, const float* __restrict__ mask,
    const float* __restrict__ A)
{
    __shared__ __align__(16) float xs[NN];
    __shared__ __align__(16) float ys[NN];
    __shared__ __align__(16) float kz[NN];
    __shared__ float redw[4][128];
    __shared__ float redd[4][128];

    const int b = blockIdx.x >> 3;
    const int jbase = (blockIdx.x & 7) * 128;
    const int t = threadIdx.x;

    // A -> Bhi/Blo bf16 (blocks 0..15; gemm launches after, so visible)
    if (blockIdx.x < 16) {
        #pragma unroll
        for (int p = 0; p < 2; p++) {
            int idx = blockIdx.x * 1024 + p * 512 + t;   // 0..16383
            int n = idx >> 7, k = idx & 127;
            float a = A[k * 128 + n];
            __nv_bfloat16 h = __float2bfloat16_rn(a);
            Bhi_g[idx] = h;
            Blo_g[idx] = __float2bfloat16_rn(a - __bfloat162float(h));
        }
    }

    for (int i = t; i < NN; i += 512) {
        float2 c = *(const float2*)(x + ((size_t)b * NN + i) * NF + (NF - 2));
        xs[i] = c.x;
        ys[i] = c.y;
        kz[i] = KC * fmaf(c.y, c.y, c.x * c.x);
    }
    __syncthreads();

    const int q  = t >> 7;        // i-quarter, uniform within each warp
    const int jl = t & 127;
    const int j  = jbase + jl;
    const float Km2jx = -2.0f * KC * xs[j];
    const float Km2jy = -2.0f * KC * ys[j];
    const float Krj = kz[j];

    const u64 Kx2 = pk2f(Km2jx, Km2jx);
    const u64 Ky2 = pk2f(Km2jy, Km2jy);
    const u64 Kr2 = pk2f(Krj, Krj);

    const ulonglong2* X2 = (const ulonglong2*)(xs) + q * 64;
    const ulonglong2* Y2 = (const ulonglong2*)(ys) + q * 64;
    const ulonglong2* Z2 = (const ulonglong2*)(kz) + q * 64;

    u64 S1A = 0ULL, S2A = 0ULL, S1B = 0ULL, S2B = 0ULL;
    #pragma unroll 4
    for (int i = 0; i < 64; i++) {          // 4 points per iteration, broadcast loads
        ulonglong2 X = X2[i];
        ulonglong2 Y = Y2[i];
        ulonglong2 Z = Z2[i];

        u64 u0; ADD2(u0, Z.x, Kr2);
        FMA2IO(u0, Y.x, Ky2);
        FMA2IO(u0, X.x, Kx2);
        float ua, ub; up2f(u0, ua, ub);
        u64 e0 = pk2f(fast_exp2(ua), fast_exp2(ub));
        ADD2ACC(S1A, e0);
        FMA2IO(S2A, u0, e0);

        u64 u1; ADD2(u1, Z.y, Kr2);
        FMA2IO(u1, Y.y, Ky2);
        FMA2IO(u1, X.y, Kx2);
        float uc, ud; up2f(u1, uc, ud);
        u64 e1 = pk2f(fast_exp2(uc), fast_exp2(ud));
        ADD2ACC(S1B, e1);
        FMA2IO(S2B, u1, e1);
    }

    float a, bb, c, d;
    up2f(S1A, a, bb); up2f(S1B, c, d);
    float s1 = (a + bb) + (c + d);
    up2f(S2A, a, bb); up2f(S2B, c, d);
    float s2 = (a + bb) + (c + d);

    redw[q][jl] = s1;
    redd[q][jl] = s2;
    __syncthreads();

    if (t < 128) {
        float ws = (redw[0][t] + redw[1][t]) + (redw[2][t] + redw[3][t]);
        float dw = (redd[0][t] + redd[1][t]) + (redd[2][t] + redd[3][t]);
        int gj = b * NN + jbase + t;
        float m = mask[gj];
        c1v_g[gj] = fmaf(ws, m, -1.0f);
        c2v_g[gj] = (dw * INV_KC) * m;
    }
}

// ---------------------------------------------------------------------------
// Kernel 2: GEMM with c1 folded in (persistent: 2 tiles per CTA).
// EXACT round-12 configuration (measured 18.5us): 256 threads (8 warps),
// warp tile 32r x 32c, grid 256, 104.4KB smem, 2 CTAs/SM.
// ---------------------------------------------------------------------------
#define XROW 272
#define OFF_GXHI 0
#define OFF_GXLO (64 * XROW)                 // 17408
#define OFF_GBHI (2 * 64 * XROW)             // 34816
#define OFF_GBLO (OFF_GBHI + 128 * XROW)     // 69632
#define GSMEM_TOTAL (OFF_GBLO + 128 * XROW)  // 104448

__global__ void __launch_bounds__(256) gemm_kernel(
    const float* __restrict__ x,
    const float* __restrict__ mask,
    const float* __restrict__ A,
    const float* __restrict__ bias,
    float* __restrict__ out)
{
    extern __shared__ __align__(16) char sm[];
    const u32 sbase = smem_u32(sm);
    const int t = threadIdx.x;
    const int wid = t >> 5;
    const int lane = t & 31;

    // ---- B tiles: bf16 globals -> padded smem rows (once per CTA) ----
    {
        const uint4* bh = (const uint4*)Bhi_g;
        const uint4* bl = (const uint4*)Blo_g;
        #pragma unroll
        for (int pass = 0; pass < 8; pass++) {
            int idx = pass * 256 + t;           // 0..2047: 128 rows x 16 chunks
            int row = idx >> 4, chunk = idx & 15;
            char* dst = sm + row * XROW + chunk * 16;
            *(uint4*)(dst + OFF_GBHI) = bh[idx];
            *(uint4*)(dst + OFF_GBLO) = bl[idx];
        }
    }

    // per-thread constants
    const int m0 = (wid & 1) * 32;       // 2 m-warps x 32 rows
    const int n0 = (wid >> 1) * 32;      // 4 n-warps x 32 cols
    const int g = lane >> 3, ri = lane & 7;
    const u32 arow = (u32)(ri + ((g & 1) << 3));
    const u32 acol = (u32)((g >> 1) << 4);
    const u32 brow = (u32)(ri + ((g >> 1) << 3));
    const u32 bcol = (u32)((g & 1) << 4);
    const u32 XhiB = sbase + OFF_GXHI + (m0 + arow) * XROW + acol;
    const u32 XloB = XhiB + (u32)(OFF_GXLO - OFF_GXHI);
    const u32 BhiB = sbase + OFF_GBHI + (n0 + brow) * XROW + bcol;
    const u32 BloB = BhiB + (u32)(OFF_GBLO - OFF_GBHI);
    const float* A2p = A + 128 * 128;

    #pragma unroll
    for (int tile = 0; tile < 2; tile++) {
        const int row0 = (blockIdx.x * 2 + tile) * 64;

        // ---- X2 = [x | c1*x] as bf16 hi/lo ----
        {
            int row  = t >> 2;                      // 0..63
            int cseg = (t & 3) * 16;                // 16 cols each
            const float* xr = x + (size_t)(row0 + row) * NF + cseg;
            float c1 = c1v_g[row0 + row];
            char* ph = sm + OFF_GXHI + row * XROW + cseg * 2;
            char* pl = sm + OFF_GXLO + row * XROW + cseg * 2;
            #pragma unroll
            for (int qq = 0; qq < 4; qq++) {
                float4 v = *(const float4*)(xr + qq * 4);
                float vs[4] = {v.x, v.y, v.z, v.w};
                u32 hi[2], lo[2], shi[2], slo[2];
                #pragma unroll
                for (int h = 0; h < 2; h++) {
                    u32 hp = 0, lp = 0, shp = 0, slp = 0;
                    #pragma unroll
                    for (int e = 0; e < 2; e++) {
                        float vv = vs[h * 2 + e];
                        __nv_bfloat16 vh = __float2bfloat16_rn(vv);
                        __nv_bfloat16 vl = __float2bfloat16_rn(vv - __bfloat162float(vh));
                        float w = c1 * vv;
                        __nv_bfloat16 wh = __float2bfloat16_rn(w);
                        __nv_bfloat16 wl = __float2bfloat16_rn(w - __bfloat162float(wh));
                        hp  |= (u32)__bfloat16_as_ushort(vh) << (16 * e);
                        lp  |= (u32)__bfloat16_as_ushort(vl) << (16 * e);
                        shp |= (u32)__bfloat16_as_ushort(wh) << (16 * e);
                        slp |= (u32)__bfloat16_as_ushort(wl) << (16 * e);
                    }
                    hi[h] = hp; lo[h] = lp; shi[h] = shp; slo[h] = slp;
                }
                *(u32*)(ph + qq * 8)           = hi[0];
                *(u32*)(ph + qq * 8 + 4)       = hi[1];
                *(u32*)(ph + 128 + qq * 8)     = shi[0];   // cols 64..127 = c1*x
                *(u32*)(ph + 128 + qq * 8 + 4) = shi[1];
                *(u32*)(pl + qq * 8)           = lo[0];
                *(u32*)(pl + qq * 8 + 4)       = lo[1];
                *(u32*)(pl + 128 + qq * 8)     = slo[0];
                *(u32*)(pl + 128 + qq * 8 + 4) = slo[1];
            }
        }
        __syncthreads();

        // ---- mainloop ----
        float acc[2][4][4];
        #pragma unroll
        for (int mt = 0; mt < 2; mt++)
            #pragma unroll
            for (int nb = 0; nb < 4; nb++)
                #pragma unroll
                for (int e = 0; e < 4; e++)
                    acc[mt][nb][e] = 0.f;

        #pragma unroll
        for (int kb = 0; kb < 8; kb++) {
            const u32 koff = kb * 32;              // 16 k-elements = 32 bytes
            u32 ah[2][4], al[2][4];
            LDSM_X4(ah[0][0], ah[0][1], ah[0][2], ah[0][3], XhiB + koff);
            LDSM_X4(ah[1][0], ah[1][1], ah[1][2], ah[1][3], XhiB + 16 * XROW + koff);
            LDSM_X4(al[0][0], al[0][1], al[0][2], al[0][3], XloB + koff);
            LDSM_X4(al[1][0], al[1][1], al[1][2], al[1][3], XloB + 16 * XROW + koff);

            u32 bh[4][2], bl[4][2];
            LDSM_X4(bh[0][0], bh[0][1], bh[1][0], bh[1][1], BhiB + koff);
            LDSM_X4(bh[2][0], bh[2][1], bh[3][0], bh[3][1], BhiB + 16 * XROW + koff);
            LDSM_X4(bl[0][0], bl[0][1], bl[1][0], bl[1][1], BloB + koff);
            LDSM_X4(bl[2][0], bl[2][1], bl[3][0], bl[3][1], BloB + 16 * XROW + koff);

            #pragma unroll
            for (int nb = 0; nb < 4; nb++) {
                #pragma unroll
                for (int mt = 0; mt < 2; mt++) {
                    mma16816(acc[mt][nb], ah[mt], bh[nb]);   // xhi * Bhi
                    mma16816(acc[mt][nb], al[mt], bh[nb]);   // xlo * Bhi
                    mma16816(acc[mt][nb], ah[mt], bl[nb]);   // xhi * Blo
                }
            }
        }

        // ---- epilogue: out = (acc + c2*A2 + bias) * m ----
        #pragma unroll
        for (int mt = 0; mt < 2; mt++) {
            const int r1 = m0 + mt * 16 + (lane >> 2);
            const int r2 = r1 + 8;
            const int gr1 = row0 + r1, gr2 = row0 + r2;
            const float m1 = mask[gr1], m2 = mask[gr2];
            const float c21 = c2v_g[gr1], c22 = c2v_g[gr2];
            #pragma unroll
            for (int nb = 0; nb < 4; nb++) {
                const int col = n0 + nb * 8 + (lane & 3) * 2;
                const float a20 = A2p[col], a21 = A2p[col + 1];
                const float b0 = bias[col], b1 = bias[col + 1];
                const float* gacc = acc[mt][nb];
                float2 o1, o2;
                o1.x = (gacc[0] + fmaf(c21, a20, b0)) * m1;
                o1.y = (gacc[1] + fmaf(c21, a21, b1)) * m1;
                o2.x = (gacc[2] + fmaf(c22, a20, b0)) * m2;
                o2.y = (gacc[3] + fmaf(c22, a21, b1)) * m2;
                *(float2*)(out + (size_t)gr1 * NO + col) = o1;
                *(float2*)(out + (size_t)gr2 * NO + col) = o2;
            }
        }
        __syncthreads();   // X2 rewrite protection for next tile
    }
}

extern "C" void kernel_launch(void* const* d_in, const int* in_sizes, int n_in,
                              void* d_out, int out_size) {
    const float* x    = (const float*)d_in[0];
    const float* mask = (const float*)d_in[1];
    const float* A    = (const float*)d_in[2];
    const float* bias = (const float*)d_in[3];
    float* out = (float*)d_out;

    cudaFuncSetAttribute(gemm_kernel, cudaFuncAttributeMaxDynamicSharedMemorySize, GSMEM_TOTAL);

    coef_kernel<<<NB * 8, 512>>>(x, mask, A);
    gemm_kernel<<<(NB * NN) / 128, 256, GSMEM_TOTAL>>>(x, mask, A, bias, out);
}